// round 14
// baseline (speedup 1.0000x reference)
#include <cuda_runtime.h>
#include <cuda_bf16.h>
#include <cuda_fp16.h>
#include <cstdint>

#define NROWS 8192
#define DDIM  256
#define KSEL  64
#define SLOT_CAP 128
#define CND 256

__device__ __constant__ float kNEG = -1.0e9f;

// ---------------- scratch (static device globals; no runtime alloc) -------------
__device__ float g_Q[(size_t)NROWS * DDIM];
__device__ float g_K[(size_t)NROWS * DDIM];
__device__ float g_V[(size_t)NROWS * DDIM];
__device__ __align__(16) __nv_bfloat16 g_S[(size_t)NROWS * NROWS];   // 128 MB approx scores
__device__ __align__(16) __half g_Qh[(size_t)NROWS * DDIM];
__device__ __align__(16) __half g_Kh[(size_t)NROWS * DDIM];

// ---------------- generic helpers ----------------
typedef unsigned long long ull;

__device__ __forceinline__ ull pack2(float lo, float hi) {
    ull r;
    asm("mov.b64 %0, {%1, %2};" : "=l"(r) : "r"(__float_as_uint(lo)), "r"(__float_as_uint(hi)));
    return r;
}
__device__ __forceinline__ void unpack2(float& lo, float& hi, ull v) {
    unsigned a, b;
    asm("mov.b64 {%0, %1}, %2;" : "=r"(a), "=r"(b) : "l"(v));
    lo = __uint_as_float(a); hi = __uint_as_float(b);
}
__device__ __forceinline__ void fma2(ull& d, ull a, ull b) {
    asm("fma.rn.f32x2 %0, %1, %2, %3;" : "=l"(d) : "l"(a), "l"(b), "l"(d));
}
__device__ __forceinline__ unsigned f2u(float f) {
    unsigned b = __float_as_uint(f);
    return (b & 0x80000000u) ? ~b : (b | 0x80000000u);
}
__device__ __forceinline__ float u2f(unsigned x) {
    unsigned b = (x & 0x80000000u) ? (x ^ 0x80000000u) : ~x;
    return __uint_as_float(b);
}
__device__ __forceinline__ uint32_t smem_u32(const void* p) {
    uint32_t a;
    asm("{ .reg .u64 t; cvta.to.shared.u64 t, %1; cvt.u32.u64 %0, t; }" : "=r"(a) : "l"(p));
    return a;
}
__device__ __forceinline__ void bf2f(uint32_t w, float& a, float& b) {
    __nv_bfloat162 h = *reinterpret_cast<__nv_bfloat162*>(&w);
    a = __bfloat162float(h.x); b = __bfloat162float(h.y);
}

// ---------------- baseline-PTX async copy + tensor-core macros ----------------
#define CP_ASYNC16(dst, src) \
    asm volatile("cp.async.cg.shared.global [%0], [%1], 16;" :: "r"(dst), "l"(src) : "memory")
#define CP_COMMIT() asm volatile("cp.async.commit_group;" ::: "memory")
#define CP_WAIT(n)  asm volatile("cp.async.wait_group %0;" :: "n"(n) : "memory")

#define LDSM_X4(r, addr) \
    asm volatile("ldmatrix.sync.aligned.m8n8.x4.shared.b16 {%0,%1,%2,%3}, [%4];" \
        : "=r"((r)[0]), "=r"((r)[1]), "=r"((r)[2]), "=r"((r)[3]) : "r"(addr))

#define MMAF16(d, a, b0, b1) \
    asm volatile("mma.sync.aligned.m16n8k16.row.col.f32.f16.f16.f32 " \
        "{%0,%1,%2,%3}, {%4,%5,%6,%7}, {%8,%9}, {%0,%1,%2,%3};" \
        : "+f"((d)[0]), "+f"((d)[1]), "+f"((d)[2]), "+f"((d)[3]) \
        : "r"((a)[0]), "r"((a)[1]), "r"((a)[2]), "r"((a)[3]), "r"(b0), "r"(b1))

#define SW128(off) ((off) ^ (((off) >> 3) & 0x70))

// ---------------- block reductions (256 threads, 8 warps) ----------------
__device__ __forceinline__ int blockSumI(int v, int* buf, int tid) {
    #pragma unroll
    for (int o = 16; o; o >>= 1) v += __shfl_down_sync(0xffffffffu, v, o);
    if ((tid & 31) == 0) buf[tid >> 5] = v;
    __syncthreads();
    if (tid < 32) {
        int t = (tid < 8) ? buf[tid] : 0;
        #pragma unroll
        for (int o = 4; o; o >>= 1) t += __shfl_down_sync(0xffffffffu, t, o);
        if (tid == 0) buf[0] = t;
    }
    __syncthreads();
    int r = buf[0];
    __syncthreads();
    return r;
}
__device__ __forceinline__ float blockSumF(float v, float* buf, int tid) {
    #pragma unroll
    for (int o = 16; o; o >>= 1) v += __shfl_down_sync(0xffffffffu, v, o);
    if ((tid & 31) == 0) buf[tid >> 5] = v;
    __syncthreads();
    if (tid < 32) {
        float t = (tid < 8) ? buf[tid] : 0.f;
        #pragma unroll
        for (int o = 4; o; o >>= 1) t += __shfl_down_sync(0xffffffffu, t, o);
        if (tid == 0) buf[0] = t;
    }
    __syncthreads();
    float r = buf[0];
    __syncthreads();
    return r;
}
__device__ __forceinline__ unsigned blockMaxU(unsigned v, unsigned* buf, int tid) {
    #pragma unroll
    for (int o = 16; o; o >>= 1) v = max(v, __shfl_down_sync(0xffffffffu, v, o));
    if ((tid & 31) == 0) buf[tid >> 5] = v;
    __syncthreads();
    if (tid < 32) {
        unsigned t = (tid < 8) ? buf[tid] : 0u;
        #pragma unroll
        for (int o = 4; o; o >>= 1) t = max(t, __shfl_down_sync(0xffffffffu, t, o));
        if (tid == 0) buf[0] = t;
    }
    __syncthreads();
    unsigned r = buf[0];
    __syncthreads();
    return r;
}

// ---------------- FFMA NT-GEMM tile core (for QKV; 128x128, BK=16) --------------
__device__ __forceinline__ void gemm_tile_nt(
    const float* __restrict__ A, const float* __restrict__ B,
    int Kd, int row0, int col0,
    float (*As)[128], float (*Bs)[128], ull acc[8][4])
{
    const int tid = threadIdx.x;
    const int tx = tid & 15, ty = tid >> 4;

    for (int kc = 0; kc < Kd; kc += 16) {
        #pragma unroll
        for (int l = 0; l < 2; l++) {
            int flat = tid + (l << 8);
            int r  = flat >> 2;
            int kq = (flat & 3) << 2;
            float4 va = *(const float4*)(A + (size_t)(row0 + r) * Kd + kc + kq);
            As[kq + 0][r] = va.x; As[kq + 1][r] = va.y;
            As[kq + 2][r] = va.z; As[kq + 3][r] = va.w;
            float4 vb = *(const float4*)(B + (size_t)(col0 + r) * Kd + kc + kq);
            Bs[kq + 0][r] = vb.x; Bs[kq + 1][r] = vb.y;
            Bs[kq + 2][r] = vb.z; Bs[kq + 3][r] = vb.w;
        }
        __syncthreads();
        #pragma unroll
        for (int kk = 0; kk < 16; kk++) {
            float4 a0 = *(const float4*)(&As[kk][ty * 4]);
            float4 a1 = *(const float4*)(&As[kk][ty * 4 + 64]);
            float4 b0 = *(const float4*)(&Bs[kk][tx * 4]);
            float4 b1 = *(const float4*)(&Bs[kk][tx * 4 + 64]);
            ull bb0 = pack2(b0.x, b0.y), bb1 = pack2(b0.z, b0.w);
            ull bb2 = pack2(b1.x, b1.y), bb3 = pack2(b1.z, b1.w);
            float av[8] = {a0.x, a0.y, a0.z, a0.w, a1.x, a1.y, a1.z, a1.w};
            #pragma unroll
            for (int i = 0; i < 8; i++) {
                ull aa = pack2(av[i], av[i]);
                fma2(acc[i][0], aa, bb0);
                fma2(acc[i][1], aa, bb1);
                fma2(acc[i][2], aa, bb2);
                fma2(acc[i][3], aa, bb3);
            }
        }
        __syncthreads();
    }
}

// ---------------- K1: QKV projections, one launch (grid.z = sel) ---------------
__global__ __launch_bounds__(256, 2)
void qkv_kernel(const float* __restrict__ X,
                const float* __restrict__ Wq, const float* __restrict__ bq,
                const float* __restrict__ Wk, const float* __restrict__ bk,
                const float* __restrict__ Wv, const float* __restrict__ bv)
{
    __shared__ float As[16][128];
    __shared__ float Bs[16][128];
    ull acc[8][4];
    #pragma unroll
    for (int i = 0; i < 8; i++)
        #pragma unroll
        for (int j = 0; j < 4; j++) acc[i][j] = 0ull;

    const int sel = blockIdx.z;
    const float* W    = (sel == 0) ? Wq : (sel == 1) ? Wk : Wv;
    const float* bias = (sel == 0) ? bq : (sel == 1) ? bk : bv;

    int row0 = blockIdx.y * 128, col0 = blockIdx.x * 128;
    gemm_tile_nt(X, W, DDIM, row0, col0, As, Bs, acc);

    float* C = (sel == 0) ? g_Q : (sel == 1) ? g_K : g_V;
    __half* H = (sel == 0) ? g_Qh : g_Kh;
    const int tid = threadIdx.x, tx = tid & 15, ty = tid >> 4;
    const int gc0 = col0 + tx * 4, gc1 = gc0 + 64;
    float4 b0 = *(const float4*)&bias[gc0];
    float4 b1 = *(const float4*)&bias[gc1];

    #pragma unroll
    for (int i = 0; i < 8; i++) {
        int grow = row0 + ty * 4 + ((i < 4) ? i : 60 + i);
        float o[8];
        unpack2(o[0], o[1], acc[i][0]);
        unpack2(o[2], o[3], acc[i][1]);
        unpack2(o[4], o[5], acc[i][2]);
        unpack2(o[6], o[7], acc[i][3]);
        o[0] += b0.x; o[1] += b0.y; o[2] += b0.z; o[3] += b0.w;
        o[4] += b1.x; o[5] += b1.y; o[6] += b1.z; o[7] += b1.w;
        *(float4*)&C[(size_t)grow * DDIM + gc0] = make_float4(o[0], o[1], o[2], o[3]);
        *(float4*)&C[(size_t)grow * DDIM + gc1] = make_float4(o[4], o[5], o[6], o[7]);
        if (sel < 2) {
            *(__half2*)&H[(size_t)grow * DDIM + gc0]     = __floats2half2_rn(o[0], o[1]);
            *(__half2*)&H[(size_t)grow * DDIM + gc0 + 2] = __floats2half2_rn(o[2], o[3]);
            *(__half2*)&H[(size_t)grow * DDIM + gc1]     = __floats2half2_rn(o[4], o[5]);
            *(__half2*)&H[(size_t)grow * DDIM + gc1 + 2] = __floats2half2_rn(o[6], o[7]);
        }
    }
}

// ---------------- K2: HMMA fp16 score GEMM (1 pass), bf16 store ---------------
#define STAGE_BYTES 32768
#define SM_SCORE_TOTAL (3 * STAGE_BYTES)
#define NCHUNK 4

__device__ __forceinline__ void issue_chunk(uint32_t sb, int c, int stage,
                                            int row0, int col0, int tid)
{
    const int kb = c * 128;
    const uint32_t da = sb + stage * STAGE_BYTES;
    const uint32_t db = da + 16384;

    #pragma unroll
    for (int i = 0; i < 4; i++) {
        int f = tid + i * 256;
        int row = f >> 3;
        int chk = (f & 7) * 16;
        uint32_t off = SW128((uint32_t)(row * 128 + chk));
        const char* ga = (const char*)(g_Qh + (size_t)(row0 + row) * DDIM) + kb + chk;
        CP_ASYNC16(da + off, ga);
        const char* gb = (const char*)(g_Kh + (size_t)(col0 + row) * DDIM) + kb + chk;
        CP_ASYNC16(db + off, gb);
    }
    CP_COMMIT();
}

__global__ __launch_bounds__(256)
void score_mma_kernel(const float* __restrict__ temp)
{
    extern __shared__ char smem[];
    const uint32_t sb = smem_u32(smem);
    const int tid = threadIdx.x, lane = tid & 31, wid = tid >> 5;
    const int wm = wid & 3, wn = wid >> 2;
    const int row0 = blockIdx.y * 128, col0 = blockIdx.x * 128;

    float acc[2][8][4];
    #pragma unroll
    for (int i = 0; i < 2; i++)
        #pragma unroll
        for (int j = 0; j < 8; j++)
            #pragma unroll
            for (int q = 0; q < 4; q++) acc[i][j][q] = 0.f;

    issue_chunk(sb, 0, 0, row0, col0, tid);
    issue_chunk(sb, 1, 1, row0, col0, tid);

    for (int c = 0; c < NCHUNK; c++) {
        if (c + 1 < NCHUNK) CP_WAIT(1); else CP_WAIT(0);
        __syncthreads();

        if (c + 2 < NCHUNK)
            issue_chunk(sb, c + 2, (c + 2) % 3, row0, col0, tid);

        const uint32_t ab = sb + (c % 3) * STAGE_BYTES;
        const uint32_t bb = ab + 16384;

        #pragma unroll
        for (int ks = 0; ks < 4; ks++) {
            uint32_t ar[2][4], br[4][4];
            #pragma unroll
            for (int mt = 0; mt < 2; mt++) {
                int row = wm * 32 + mt * 16 + (lane & 15);
                int kby = ks * 32 + ((lane >> 4) << 4);
                uint32_t addr = ab + SW128((uint32_t)(row * 128 + kby));
                LDSM_X4(ar[mt], addr);
            }
            #pragma unroll
            for (int pt = 0; pt < 4; pt++) {
                int n   = wn * 64 + pt * 16 + (lane & 7) + ((lane >> 4) << 3);
                int kby = ks * 32 + (((lane >> 3) & 1) << 4);
                uint32_t addr = bb + SW128((uint32_t)(n * 128 + kby));
                LDSM_X4(br[pt], addr);
            }
            #pragma unroll
            for (int mt = 0; mt < 2; mt++)
                #pragma unroll
                for (int pt = 0; pt < 4; pt++) {
                    MMAF16(acc[mt][2 * pt],     ar[mt], br[pt][0], br[pt][1]);
                    MMAF16(acc[mt][2 * pt + 1], ar[mt], br[pt][2], br[pt][3]);
                }
        }
    }

    const float scale = 1.0f / (__ldg(temp) * 16.0f);
    #pragma unroll
    for (int mt = 0; mt < 2; mt++) {
        const int r0g = row0 + wm * 32 + mt * 16 + (lane >> 2);
        const int r1g = r0g + 8;
        #pragma unroll
        for (int nt = 0; nt < 8; nt++) {
            const int gc = col0 + wn * 64 + nt * 8 + (lane & 3) * 2;
            float v00 = (r0g == gc)     ? kNEG : acc[mt][nt][0] * scale;
            float v01 = (r0g == gc + 1) ? kNEG : acc[mt][nt][1] * scale;
            float v10 = (r1g == gc)     ? kNEG : acc[mt][nt][2] * scale;
            float v11 = (r1g == gc + 1) ? kNEG : acc[mt][nt][3] * scale;
            __nv_bfloat162 h0, h1;
            h0.x = __float2bfloat16(v00); h0.y = __float2bfloat16(v01);
            h1.x = __float2bfloat16(v10); h1.y = __float2bfloat16(v11);
            *(__nv_bfloat162*)&g_S[(size_t)r0g * NROWS + gc] = h0;
            *(__nv_bfloat162*)&g_S[(size_t)r1g * NROWS + gc] = h1;
        }
    }
}

// ---------------- K3: fused certified top-64 + exact re-score + output --------
// R10 structure with higher MLP; warp-UNIFORM candidate loop (cb uniform per
// warp, per-lane c predicated) so full-mask shuffles are legal.
__global__ __launch_bounds__(256, 4)
void topk_out_kernel(const float* __restrict__ temp, float* __restrict__ out)
{
    const int row = blockIdx.x;
    const int tid = threadIdx.x, lane = tid & 31, wd = tid >> 5;

    __shared__ __align__(16) __nv_bfloat16 srowS[NROWS];   // 16 KB row cache
    __shared__ float sQ[DDIM];
    __shared__ int   candCol[CND];
    __shared__ float exS[CND];
    __shared__ int   sidx[SLOT_CAP];
    __shared__ float se[SLOT_CAP];
    __shared__ int   hist[8][16];
    __shared__ int   red_i[8];
    __shared__ float red_f[8];
    __shared__ unsigned red_u[8];
    __shared__ float s_cutHi;
    __shared__ int   s_cand, s_total, s_fb;

    // ---- pass 1: DRAM -> SMEM, row max + mean (excluding diagonal NEG) ----
    const uint4* __restrict__ src = (const uint4*)(g_S + (size_t)row * NROWS);
    uint4* dst = (uint4*)srowS;
    float lmax = -3.0e38f, lsum = 0.f;
    #pragma unroll
    for (int i = 0; i < 4; i++) {
        const int idx = tid + i * 256;
        uint4 w = src[idx];
        dst[idx] = w;
        float a, b;
        bf2f(w.x, a, b);
        if (a > -1e8f) { lsum += a; lmax = fmaxf(lmax, a); }
        if (b > -1e8f) { lsum += b; lmax = fmaxf(lmax, b); }
        bf2f(w.y, a, b);
        if (a > -1e8f) { lsum += a; lmax = fmaxf(lmax, a); }
        if (b > -1e8f) { lsum += b; lmax = fmaxf(lmax, b); }
        bf2f(w.z, a, b);
        if (a > -1e8f) { lsum += a; lmax = fmaxf(lmax, a); }
        if (b > -1e8f) { lsum += b; lmax = fmaxf(lmax, b); }
        bf2f(w.w, a, b);
        if (a > -1e8f) { lsum += a; lmax = fmaxf(lmax, a); }
        if (b > -1e8f) { lsum += b; lmax = fmaxf(lmax, b); }
    }
    const float m = u2f(blockMaxU(f2u(lmax), red_u, tid));
    const float mean = blockSumF(lsum, red_f, tid) * (1.0f / (float)(NROWS - 1));

    // ---- histogram: 16 buckets over top half of (mean, m] ----
    if (tid < 128) hist[tid >> 4][tid & 15] = 0;
    if (tid == 0) { s_cand = 0; s_fb = 0; }
    __syncthreads();

    const float delta = (m - mean) * (1.0f / 32.0f);
    const bool degen = !(delta > 0.f);
    if (!degen) {
        const float invd = 1.0f / delta;
        #pragma unroll
        for (int i = 0; i < 4; i++) {
            const int idx = tid + i * 256;
            uint4 w = dst[idx];
            float v[8];
            bf2f(w.x, v[0], v[1]); bf2f(w.y, v[2], v[3]);
            bf2f(w.z, v[4], v[5]); bf2f(w.w, v[6], v[7]);
            #pragma unroll
            for (int j = 0; j < 8; j++) {
                int b = (int)((m - v[j]) * invd);
                if (b < 16) atomicAdd(&hist[wd][b < 0 ? 0 : b], 1);
            }
        }
    }
    __syncthreads();
    if (tid < 16) {
        int s = 0;
        #pragma unroll
        for (int w = 0; w < 8; w++) s += hist[w][tid];
        hist[0][tid] = s;
    }
    __syncthreads();
    if (tid == 0) {
        int cum = 0, b = -1;
        for (int i = 0; i < 16; i++) { cum += hist[0][i]; if (cum >= KSEL) { b = i; break; } }
        if (degen || b < 0) s_fb = 1;
        else s_cutHi = m - (float)(b + 1) * delta;
    }
    __syncthreads();

    // ---- rare fallback: full 32-bit bisection -> exact 64th ----
    bool ranFB = (s_fb != 0);
    if (ranFB) {
        unsigned pfx = 0;
        for (int bit = 31; bit >= 0; bit--) {
            unsigned t = pfx | (1u << bit);
            int c = 0;
            #pragma unroll
            for (int i = 0; i < 4; i++) {
                uint4 w = dst[tid + i * 256];
                float v[8];
                bf2f(w.x, v[0], v[1]); bf2f(w.y, v[2], v[3]);
                bf2f(w.z, v[4], v[5]); bf2f(w.w, v[6], v[7]);
                #pragma unroll
                for (int j = 0; j < 8; j++) c += (f2u(v[j]) >= t);
            }
            if (blockSumI(c, red_i, tid) >= KSEL) pfx = t;
        }
        if (tid == 0) s_cutHi = u2f(pfx);
        __syncthreads();
    }

    // ---- candidate collection: approx >= cutHi - 2*EPS ----
    const float scale = 1.0f / (__ldg(temp) * 16.0f);
    float cutHi = s_cutHi;
    const float EPS = 0.5f * scale + 0.02f * fmaxf(fabsf(cutHi), 1.0f);
    float cutoff = cutHi - 2.0f * EPS;

    for (int attempt = 0; attempt < 2; attempt++) {
        #pragma unroll
        for (int i = 0; i < 4; i++) {
            const int idx = tid + i * 256;
            uint4 w = dst[idx];
            float v[8];
            bf2f(w.x, v[0], v[1]); bf2f(w.y, v[2], v[3]);
            bf2f(w.z, v[4], v[5]); bf2f(w.w, v[6], v[7]);
            #pragma unroll
            for (int j = 0; j < 8; j++) {
                if (v[j] >= cutoff) {
                    int p = atomicAdd(&s_cand, 1);
                    if (p < CND) candCol[p] = idx * 8 + j;
                }
            }
        }
        sQ[tid] = g_Q[(size_t)row * DDIM + tid];
        __syncthreads();
        if (s_cand <= CND || ranFB) break;
        ranFB = true;
        unsigned pfx = 0;
        for (int bit = 31; bit >= 0; bit--) {
            unsigned t = pfx | (1u << bit);
            int c = 0;
            #pragma unroll
            for (int i = 0; i < 4; i++) {
                uint4 w = dst[tid + i * 256];
                float v[8];
                bf2f(w.x, v[0], v[1]); bf2f(w.y, v[2], v[3]);
                bf2f(w.z, v[4], v[5]); bf2f(w.w, v[6], v[7]);
                #pragma unroll
                for (int j = 0; j < 8; j++) c += (f2u(v[j]) >= t);
            }
            if (blockSumI(c, red_i, tid) >= KSEL) pfx = t;
        }
        if (tid == 0) { s_cutHi = u2f(pfx); s_cand = 0; }
        __syncthreads();
        cutHi = s_cutHi;
        cutoff = cutHi - 2.0f * EPS;
    }
    const int ncand = min(s_cand, CND);

    // ---- exact fp32 dots: 4 candidates per warp per iteration (warp-uniform) --
    // cb is uniform across the warp; per-lane candidate c = cb + g is predicated.
    {
        const int g = lane >> 3, sl = lane & 7;
        const int e0 = sl * 32;
        const float* __restrict__ qrow = sQ + e0;
        for (int cb = wd * 4; cb < ncand; cb += 32) {     // uniform trip count
            const int c = cb + g;
            const bool valid = (c < ncand);
            const int cc = valid ? candCol[c] : candCol[cb];   // safe clamp
            const float* __restrict__ krow = g_K + (size_t)cc * DDIM + e0;
            float part = 0.f;
            #pragma unroll
            for (int e = 0; e < 32; e += 4) {
                float4 qa = *(const float4*)(qrow + e);
                float4 ka = *(const float4*)(krow + e);
                part += qa.x * ka.x + qa.y * ka.y + qa.z * ka.z + qa.w * ka.w;
            }
            part += __shfl_down_sync(0xffffffffu, part, 4);
            part += __shfl_down_sync(0xffffffffu, part, 2);
            part += __shfl_down_sync(0xffffffffu, part, 1);
            if (sl == 0 && valid) exS[c] = part * scale;
        }
    }
    __syncthreads();

    // ---- exact ranking: keep rank < KSEL (ties kept, matching reference) ----
    int myKept = 0;
    float myExp = 0.f;
    if (tid < ncand) {
        float v = exS[tid];
        int cg = 0;
        for (int j = 0; j < ncand; j++) cg += (exS[j] > v);
        if (cg < KSEL) { myKept = 1; myExp = expf(v - m); }
    }

    // ---- ballot-scan compaction ----
    {
        unsigned bal = __ballot_sync(0xffffffffu, myKept);
        int pre = __popc(bal & ((1u << lane) - 1u));
        if (lane == 0) red_i[wd] = __popc(bal);
        __syncthreads();
        if (tid == 0) {
            int acc0 = 0;
            for (int i = 0; i < 8; i++) { int t = red_i[i]; red_i[i] = acc0; acc0 += t; }
            s_total = acc0;
        }
        __syncthreads();
        if (myKept) {
            int slot = red_i[wd] + pre;
            if (slot < SLOT_CAP) {
                sidx[slot] = candCol[tid];
                se[slot]   = myExp;
            }
        }
    }

    float tot = blockSumF(myExp, red_f, tid);
    __syncthreads();

    // ---- fused output gather: 8 independent accumulators (MLP 8) ----
    const int cnt = min(s_total, SLOT_CAP);
    const float inv = 1.0f / tot;

    float a0 = 0.f, a1 = 0.f, a2 = 0.f, a3 = 0.f;
    float a4 = 0.f, a5 = 0.f, a6 = 0.f, a7 = 0.f;
    int j = 0;
    for (; j + 8 <= cnt; j += 8) {
        a0 += se[j + 0] * g_V[(size_t)sidx[j + 0] * DDIM + tid];
        a1 += se[j + 1] * g_V[(size_t)sidx[j + 1] * DDIM + tid];
        a2 += se[j + 2] * g_V[(size_t)sidx[j + 2] * DDIM + tid];
        a3 += se[j + 3] * g_V[(size_t)sidx[j + 3] * DDIM + tid];
        a4 += se[j + 4] * g_V[(size_t)sidx[j + 4] * DDIM + tid];
        a5 += se[j + 5] * g_V[(size_t)sidx[j + 5] * DDIM + tid];
        a6 += se[j + 6] * g_V[(size_t)sidx[j + 6] * DDIM + tid];
        a7 += se[j + 7] * g_V[(size_t)sidx[j + 7] * DDIM + tid];
    }
    for (; j < cnt; j++) a0 += se[j] * g_V[(size_t)sidx[j] * DDIM + tid];

    out[(size_t)row * DDIM + tid] =
        ((a0 + a1) + (a2 + a3) + ((a4 + a5) + (a6 + a7))) * inv;
}

// ---------------- launch ----------------
extern "C" void kernel_launch(void* const* d_in, const int* in_sizes, int n_in,
                              void* d_out, int out_size)
{
    const float* X    = (const float*)d_in[0];
    const float* Wq   = (const float*)d_in[1];
    const float* bq   = (const float*)d_in[2];
    const float* Wk   = (const float*)d_in[3];
    const float* bk   = (const float*)d_in[4];
    const float* Wv   = (const float*)d_in[5];
    const float* bv   = (const float*)d_in[6];
    const float* temp = (const float*)d_in[7];
    float* out = (float*)d_out;

    cudaFuncSetAttribute(score_mma_kernel,
                         cudaFuncAttributeMaxDynamicSharedMemorySize, SM_SCORE_TOTAL);

    dim3 blk(256);
    dim3 gQKV(DDIM / 128, NROWS / 128, 3);
    qkv_kernel<<<gQKV, blk>>>(X, Wq, bq, Wk, bk, Wv, bv);

    dim3 gS(NROWS / 128, NROWS / 128);
    score_mma_kernel<<<gS, blk, SM_SCORE_TOTAL>>>(temp);

    topk_out_kernel<<<NROWS, blk>>>(temp, out);
}

// round 16
// speedup vs baseline: 1.4516x; 1.4516x over previous
#include <cuda_runtime.h>
#include <cuda_bf16.h>
#include <cuda_fp16.h>
#include <cstdint>

#define NROWS 8192
#define DDIM  256
#define KSEL  64
#define SLOT_CAP 128
#define CND 256

__device__ __constant__ float kNEG = -1.0e9f;

// ---------------- scratch (static device globals; no runtime alloc) -------------
__device__ float g_Q[(size_t)NROWS * DDIM];
__device__ float g_K[(size_t)NROWS * DDIM];
__device__ float g_V[(size_t)NROWS * DDIM];
__device__ __align__(16) __nv_bfloat16 g_S[(size_t)NROWS * NROWS];   // 128 MB approx scores
__device__ __align__(16) __half g_Qh[(size_t)NROWS * DDIM];
__device__ __align__(16) __half g_Kh[(size_t)NROWS * DDIM];

// ---------------- generic helpers ----------------
typedef unsigned long long ull;

__device__ __forceinline__ ull pack2(float lo, float hi) {
    ull r;
    asm("mov.b64 %0, {%1, %2};" : "=l"(r) : "r"(__float_as_uint(lo)), "r"(__float_as_uint(hi)));
    return r;
}
__device__ __forceinline__ void unpack2(float& lo, float& hi, ull v) {
    unsigned a, b;
    asm("mov.b64 {%0, %1}, %2;" : "=r"(a), "=r"(b) : "l"(v));
    lo = __uint_as_float(a); hi = __uint_as_float(b);
}
__device__ __forceinline__ void fma2(ull& d, ull a, ull b) {
    asm("fma.rn.f32x2 %0, %1, %2, %3;" : "=l"(d) : "l"(a), "l"(b), "l"(d));
}
__device__ __forceinline__ unsigned f2u(float f) {
    unsigned b = __float_as_uint(f);
    return (b & 0x80000000u) ? ~b : (b | 0x80000000u);
}
__device__ __forceinline__ float u2f(unsigned x) {
    unsigned b = (x & 0x80000000u) ? (x ^ 0x80000000u) : ~x;
    return __uint_as_float(b);
}
__device__ __forceinline__ uint32_t smem_u32(const void* p) {
    uint32_t a;
    asm("{ .reg .u64 t; cvta.to.shared.u64 t, %1; cvt.u32.u64 %0, t; }" : "=r"(a) : "l"(p));
    return a;
}
__device__ __forceinline__ void bf2f(uint32_t w, float& a, float& b) {
    __nv_bfloat162 h = *reinterpret_cast<__nv_bfloat162*>(&w);
    a = __bfloat162float(h.x); b = __bfloat162float(h.y);
}
// named barrier for 128-thread sub-block r (ids 1,2)
__device__ __forceinline__ void barx(int r) {
    asm volatile("bar.sync %0, %1;" :: "r"(1 + r), "r"(128) : "memory");
}

// ---------------- baseline-PTX async copy + tensor-core macros ----------------
#define CP_ASYNC16(dst, src) \
    asm volatile("cp.async.cg.shared.global [%0], [%1], 16;" :: "r"(dst), "l"(src) : "memory")
#define CP_COMMIT() asm volatile("cp.async.commit_group;" ::: "memory")
#define CP_WAIT(n)  asm volatile("cp.async.wait_group %0;" :: "n"(n) : "memory")

#define LDSM_X4(r, addr) \
    asm volatile("ldmatrix.sync.aligned.m8n8.x4.shared.b16 {%0,%1,%2,%3}, [%4];" \
        : "=r"((r)[0]), "=r"((r)[1]), "=r"((r)[2]), "=r"((r)[3]) : "r"(addr))

#define MMAF16(d, a, b0, b1) \
    asm volatile("mma.sync.aligned.m16n8k16.row.col.f32.f16.f16.f32 " \
        "{%0,%1,%2,%3}, {%4,%5,%6,%7}, {%8,%9}, {%0,%1,%2,%3};" \
        : "+f"((d)[0]), "+f"((d)[1]), "+f"((d)[2]), "+f"((d)[3]) \
        : "r"((a)[0]), "r"((a)[1]), "r"((a)[2]), "r"((a)[3]), "r"(b0), "r"(b1))

#define SW128(off) ((off) ^ (((off) >> 3) & 0x70))

// ---------------- block reductions (score path helpers) ----------------
__device__ __forceinline__ int blockSumI(int v, int* buf, int tid) {
    #pragma unroll
    for (int o = 16; o; o >>= 1) v += __shfl_down_sync(0xffffffffu, v, o);
    if ((tid & 31) == 0) buf[tid >> 5] = v;
    __syncthreads();
    if (tid < 32) {
        int t = (tid < 8) ? buf[tid] : 0;
        #pragma unroll
        for (int o = 4; o; o >>= 1) t += __shfl_down_sync(0xffffffffu, t, o);
        if (tid == 0) buf[0] = t;
    }
    __syncthreads();
    int r = buf[0];
    __syncthreads();
    return r;
}

// ---------------- sub-block (4-warp) reductions for warp-split topk ------------
__device__ __forceinline__ float subSumF(float v, volatile float* buf4,
                                         int r, int w4, int lane) {
    #pragma unroll
    for (int o = 16; o; o >>= 1) v += __shfl_down_sync(0xffffffffu, v, o);
    if (lane == 0) buf4[w4] = v;
    barx(r);
    float s = buf4[0] + buf4[1] + buf4[2] + buf4[3];
    barx(r);
    return s;
}
__device__ __forceinline__ int subSumI(int v, volatile int* buf4,
                                       int r, int w4, int lane) {
    #pragma unroll
    for (int o = 16; o; o >>= 1) v += __shfl_down_sync(0xffffffffu, v, o);
    if (lane == 0) buf4[w4] = v;
    barx(r);
    int s = buf4[0] + buf4[1] + buf4[2] + buf4[3];
    barx(r);
    return s;
}
__device__ __forceinline__ unsigned subMaxU(unsigned v, volatile unsigned* buf4,
                                            int r, int w4, int lane) {
    #pragma unroll
    for (int o = 16; o; o >>= 1) v = max(v, __shfl_down_sync(0xffffffffu, v, o));
    if (lane == 0) buf4[w4] = v;
    barx(r);
    unsigned s = max(max(buf4[0], buf4[1]), max(buf4[2], buf4[3]));
    barx(r);
    return s;
}

// ---------------- FFMA NT-GEMM tile core (for QKV; 128x128, BK=16) --------------
__device__ __forceinline__ void gemm_tile_nt(
    const float* __restrict__ A, const float* __restrict__ B,
    int Kd, int row0, int col0,
    float (*As)[128], float (*Bs)[128], ull acc[8][4])
{
    const int tid = threadIdx.x;
    const int tx = tid & 15, ty = tid >> 4;

    for (int kc = 0; kc < Kd; kc += 16) {
        #pragma unroll
        for (int l = 0; l < 2; l++) {
            int flat = tid + (l << 8);
            int r  = flat >> 2;
            int kq = (flat & 3) << 2;
            float4 va = *(const float4*)(A + (size_t)(row0 + r) * Kd + kc + kq);
            As[kq + 0][r] = va.x; As[kq + 1][r] = va.y;
            As[kq + 2][r] = va.z; As[kq + 3][r] = va.w;
            float4 vb = *(const float4*)(B + (size_t)(col0 + r) * Kd + kc + kq);
            Bs[kq + 0][r] = vb.x; Bs[kq + 1][r] = vb.y;
            Bs[kq + 2][r] = vb.z; Bs[kq + 3][r] = vb.w;
        }
        __syncthreads();
        #pragma unroll
        for (int kk = 0; kk < 16; kk++) {
            float4 a0 = *(const float4*)(&As[kk][ty * 4]);
            float4 a1 = *(const float4*)(&As[kk][ty * 4 + 64]);
            float4 b0 = *(const float4*)(&Bs[kk][tx * 4]);
            float4 b1 = *(const float4*)(&Bs[kk][tx * 4 + 64]);
            ull bb0 = pack2(b0.x, b0.y), bb1 = pack2(b0.z, b0.w);
            ull bb2 = pack2(b1.x, b1.y), bb3 = pack2(b1.z, b1.w);
            float av[8] = {a0.x, a0.y, a0.z, a0.w, a1.x, a1.y, a1.z, a1.w};
            #pragma unroll
            for (int i = 0; i < 8; i++) {
                ull aa = pack2(av[i], av[i]);
                fma2(acc[i][0], aa, bb0);
                fma2(acc[i][1], aa, bb1);
                fma2(acc[i][2], aa, bb2);
                fma2(acc[i][3], aa, bb3);
            }
        }
        __syncthreads();
    }
}

// ---------------- K1: QKV projections (C = X @ W^T + b), fp16 copy fused --------
__global__ __launch_bounds__(256, 2)
void qkv_kernel(const float* __restrict__ X, const float* __restrict__ W,
                const float* __restrict__ bias, int sel)
{
    __shared__ float As[16][128];
    __shared__ float Bs[16][128];
    ull acc[8][4];
    #pragma unroll
    for (int i = 0; i < 8; i++)
        #pragma unroll
        for (int j = 0; j < 4; j++) acc[i][j] = 0ull;

    int row0 = blockIdx.y * 128, col0 = blockIdx.x * 128;
    gemm_tile_nt(X, W, DDIM, row0, col0, As, Bs, acc);

    float* C = (sel == 0) ? g_Q : (sel == 1) ? g_K : g_V;
    __half* H = (sel == 0) ? g_Qh : g_Kh;
    const int tid = threadIdx.x, tx = tid & 15, ty = tid >> 4;
    const int gc0 = col0 + tx * 4, gc1 = gc0 + 64;
    float4 b0 = *(const float4*)&bias[gc0];
    float4 b1 = *(const float4*)&bias[gc1];

    #pragma unroll
    for (int i = 0; i < 8; i++) {
        int grow = row0 + ty * 4 + ((i < 4) ? i : 60 + i);
        float o[8];
        unpack2(o[0], o[1], acc[i][0]);
        unpack2(o[2], o[3], acc[i][1]);
        unpack2(o[4], o[5], acc[i][2]);
        unpack2(o[6], o[7], acc[i][3]);
        o[0] += b0.x; o[1] += b0.y; o[2] += b0.z; o[3] += b0.w;
        o[4] += b1.x; o[5] += b1.y; o[6] += b1.z; o[7] += b1.w;
        *(float4*)&C[(size_t)grow * DDIM + gc0] = make_float4(o[0], o[1], o[2], o[3]);
        *(float4*)&C[(size_t)grow * DDIM + gc1] = make_float4(o[4], o[5], o[6], o[7]);
        if (sel < 2) {
            *(__half2*)&H[(size_t)grow * DDIM + gc0]     = __floats2half2_rn(o[0], o[1]);
            *(__half2*)&H[(size_t)grow * DDIM + gc0 + 2] = __floats2half2_rn(o[2], o[3]);
            *(__half2*)&H[(size_t)grow * DDIM + gc1]     = __floats2half2_rn(o[4], o[5]);
            *(__half2*)&H[(size_t)grow * DDIM + gc1 + 2] = __floats2half2_rn(o[6], o[7]);
        }
    }
}

// ---------------- K2: HMMA fp16 score GEMM (1 pass), bf16 store ---------------
#define STAGE_BYTES 32768
#define SM_SCORE_TOTAL (3 * STAGE_BYTES)
#define NCHUNK 4

__device__ __forceinline__ void issue_chunk(uint32_t sb, int c, int stage,
                                            int row0, int col0, int tid)
{
    const int kb = c * 128;
    const uint32_t da = sb + stage * STAGE_BYTES;
    const uint32_t db = da + 16384;

    #pragma unroll
    for (int i = 0; i < 4; i++) {
        int f = tid + i * 256;
        int row = f >> 3;
        int chk = (f & 7) * 16;
        uint32_t off = SW128((uint32_t)(row * 128 + chk));
        const char* ga = (const char*)(g_Qh + (size_t)(row0 + row) * DDIM) + kb + chk;
        CP_ASYNC16(da + off, ga);
        const char* gb = (const char*)(g_Kh + (size_t)(col0 + row) * DDIM) + kb + chk;
        CP_ASYNC16(db + off, gb);
    }
    CP_COMMIT();
}

__global__ __launch_bounds__(256)
void score_mma_kernel(const float* __restrict__ temp)
{
    extern __shared__ char smem[];
    const uint32_t sb = smem_u32(smem);
    const int tid = threadIdx.x, lane = tid & 31, wid = tid >> 5;
    const int wm = wid & 3, wn = wid >> 2;
    const int row0 = blockIdx.y * 128, col0 = blockIdx.x * 128;

    float acc[2][8][4];
    #pragma unroll
    for (int i = 0; i < 2; i++)
        #pragma unroll
        for (int j = 0; j < 8; j++)
            #pragma unroll
            for (int q = 0; q < 4; q++) acc[i][j][q] = 0.f;

    issue_chunk(sb, 0, 0, row0, col0, tid);
    issue_chunk(sb, 1, 1, row0, col0, tid);

    for (int c = 0; c < NCHUNK; c++) {
        if (c + 1 < NCHUNK) CP_WAIT(1); else CP_WAIT(0);
        __syncthreads();

        if (c + 2 < NCHUNK)
            issue_chunk(sb, c + 2, (c + 2) % 3, row0, col0, tid);

        const uint32_t ab = sb + (c % 3) * STAGE_BYTES;
        const uint32_t bb = ab + 16384;

        #pragma unroll
        for (int ks = 0; ks < 4; ks++) {
            uint32_t ar[2][4], br[4][4];
            #pragma unroll
            for (int mt = 0; mt < 2; mt++) {
                int row = wm * 32 + mt * 16 + (lane & 15);
                int kby = ks * 32 + ((lane >> 4) << 4);
                uint32_t addr = ab + SW128((uint32_t)(row * 128 + kby));
                LDSM_X4(ar[mt], addr);
            }
            #pragma unroll
            for (int pt = 0; pt < 4; pt++) {
                int n   = wn * 64 + pt * 16 + (lane & 7) + ((lane >> 4) << 3);
                int kby = ks * 32 + (((lane >> 3) & 1) << 4);
                uint32_t addr = bb + SW128((uint32_t)(n * 128 + kby));
                LDSM_X4(br[pt], addr);
            }
            #pragma unroll
            for (int mt = 0; mt < 2; mt++)
                #pragma unroll
                for (int pt = 0; pt < 4; pt++) {
                    MMAF16(acc[mt][2 * pt],     ar[mt], br[pt][0], br[pt][1]);
                    MMAF16(acc[mt][2 * pt + 1], ar[mt], br[pt][2], br[pt][3]);
                }
        }
    }

    const float scale = 1.0f / (__ldg(temp) * 16.0f);
    #pragma unroll
    for (int mt = 0; mt < 2; mt++) {
        const int r0g = row0 + wm * 32 + mt * 16 + (lane >> 2);
        const int r1g = r0g + 8;
        #pragma unroll
        for (int nt = 0; nt < 8; nt++) {
            const int gc = col0 + wn * 64 + nt * 8 + (lane & 3) * 2;
            float v00 = (r0g == gc)     ? kNEG : acc[mt][nt][0] * scale;
            float v01 = (r0g == gc + 1) ? kNEG : acc[mt][nt][1] * scale;
            float v10 = (r1g == gc)     ? kNEG : acc[mt][nt][2] * scale;
            float v11 = (r1g == gc + 1) ? kNEG : acc[mt][nt][3] * scale;
            __nv_bfloat162 h0, h1;
            h0.x = __float2bfloat16(v00); h0.y = __float2bfloat16(v01);
            h1.x = __float2bfloat16(v10); h1.y = __float2bfloat16(v11);
            *(__nv_bfloat162*)&g_S[(size_t)r0g * NROWS + gc] = h0;
            *(__nv_bfloat162*)&g_S[(size_t)r1g * NROWS + gc] = h1;
        }
    }
}

// ---------------- K3: warp-split topk+out — 2 rows per block ------------------
// Warps 0-3 process row 2*blk, warps 4-7 row 2*blk+1, independent via named
// barriers. Row = 1024 uint4 = 8 iterations of 128 threads (R15 bug: was 4).
__global__ __launch_bounds__(256, 4)
void topk_out_kernel(const float* __restrict__ temp, float* __restrict__ out)
{
    const int tid  = threadIdx.x;
    const int r    = tid >> 7;          // sub-block 0/1
    const int tid4 = tid & 127;
    const int w4   = tid4 >> 5;
    const int lane = tid & 31;
    const int row  = blockIdx.x * 2 + r;

    __shared__ __align__(16) __nv_bfloat16 srowS[2][NROWS];   // 32 KB
    __shared__ float sQ[2][DDIM];
    __shared__ int   candCol[2][CND];
    __shared__ float exS[2][CND];
    __shared__ int   sidx[2][SLOT_CAP];
    __shared__ float se[2][SLOT_CAP];
    __shared__ int   hist[2][4][16];
    __shared__ int   histsum[2][16];
    __shared__ int   red_i[2][4];
    __shared__ float red_f[2][4];
    __shared__ unsigned red_u[2][4];
    __shared__ int   cw0[2][4], cw1[2][4];
    __shared__ float s_cutHi[2];
    __shared__ int   s_cand[2], s_fb[2];

    // ---- pass 1: DRAM -> SMEM, row max + mean (excluding diagonal NEG) ----
    const uint4* __restrict__ src = (const uint4*)(g_S + (size_t)row * NROWS);
    uint4* dst = (uint4*)srowS[r];
    float lmax = -3.0e38f, lsum = 0.f;
    #pragma unroll
    for (int i = 0; i < 8; i++) {
        const int idx = tid4 + i * 128;
        uint4 w = src[idx];
        dst[idx] = w;
        float a, b;
        bf2f(w.x, a, b);
        if (a > -1e8f) { lsum += a; lmax = fmaxf(lmax, a); }
        if (b > -1e8f) { lsum += b; lmax = fmaxf(lmax, b); }
        bf2f(w.y, a, b);
        if (a > -1e8f) { lsum += a; lmax = fmaxf(lmax, a); }
        if (b > -1e8f) { lsum += b; lmax = fmaxf(lmax, b); }
        bf2f(w.z, a, b);
        if (a > -1e8f) { lsum += a; lmax = fmaxf(lmax, a); }
        if (b > -1e8f) { lsum += b; lmax = fmaxf(lmax, b); }
        bf2f(w.w, a, b);
        if (a > -1e8f) { lsum += a; lmax = fmaxf(lmax, a); }
        if (b > -1e8f) { lsum += b; lmax = fmaxf(lmax, b); }
    }
    const float m = u2f(subMaxU(f2u(lmax), red_u[r], r, w4, lane));
    const float mean = subSumF(lsum, red_f[r], r, w4, lane) * (1.0f / (float)(NROWS - 1));

    // ---- histogram: 16 buckets over top half of (mean, m] ----
    if (tid4 < 64) hist[r][tid4 >> 4][tid4 & 15] = 0;
    if (tid4 == 0) { s_cand[r] = 0; s_fb[r] = 0; }
    barx(r);

    const float delta = (m - mean) * (1.0f / 32.0f);
    const bool degen = !(delta > 0.f);
    if (!degen) {
        const float invd = 1.0f / delta;
        #pragma unroll
        for (int i = 0; i < 8; i++) {
            const int idx = tid4 + i * 128;
            uint4 w = dst[idx];
            float v[8];
            bf2f(w.x, v[0], v[1]); bf2f(w.y, v[2], v[3]);
            bf2f(w.z, v[4], v[5]); bf2f(w.w, v[6], v[7]);
            #pragma unroll
            for (int j = 0; j < 8; j++) {
                int b = (int)((m - v[j]) * invd);
                if (b < 16) atomicAdd(&hist[r][w4][b < 0 ? 0 : b], 1);
            }
        }
    }
    barx(r);
    if (tid4 < 16) {
        int s = 0;
        #pragma unroll
        for (int w = 0; w < 4; w++) s += hist[r][w][tid4];
        histsum[r][tid4] = s;
    }
    barx(r);
    if (tid4 == 0) {
        int cum = 0, b = -1;
        for (int i = 0; i < 16; i++) { cum += histsum[r][i]; if (cum >= KSEL) { b = i; break; } }
        if (degen || b < 0) s_fb[r] = 1;
        else s_cutHi[r] = m - (float)(b + 1) * delta;
    }
    barx(r);

    // ---- rare fallback: full 32-bit bisection -> exact 64th ----
    bool ranFB = (s_fb[r] != 0);
    if (ranFB) {
        unsigned pfx = 0;
        for (int bit = 31; bit >= 0; bit--) {
            unsigned t = pfx | (1u << bit);
            int c = 0;
            #pragma unroll
            for (int i = 0; i < 8; i++) {
                uint4 w = dst[tid4 + i * 128];
                float v[8];
                bf2f(w.x, v[0], v[1]); bf2f(w.y, v[2], v[3]);
                bf2f(w.z, v[4], v[5]); bf2f(w.w, v[6], v[7]);
                #pragma unroll
                for (int j = 0; j < 8; j++) c += (f2u(v[j]) >= t);
            }
            if (subSumI(c, red_i[r], r, w4, lane) >= KSEL) pfx = t;
        }
        if (tid4 == 0) s_cutHi[r] = u2f(pfx);
        barx(r);
    }

    // ---- candidate collection: approx >= cutHi - 2*EPS ----
    const float scale = 1.0f / (__ldg(temp) * 16.0f);
    float cutHi = s_cutHi[r];
    const float EPS = 0.5f * scale + 0.02f * fmaxf(fabsf(cutHi), 1.0f);
    float cutoff = cutHi - 2.0f * EPS;

    for (int attempt = 0; attempt < 2; attempt++) {
        #pragma unroll
        for (int i = 0; i < 8; i++) {
            const int idx = tid4 + i * 128;
            uint4 w = dst[idx];
            float v[8];
            bf2f(w.x, v[0], v[1]); bf2f(w.y, v[2], v[3]);
            bf2f(w.z, v[4], v[5]); bf2f(w.w, v[6], v[7]);
            #pragma unroll
            for (int j = 0; j < 8; j++) {
                if (v[j] >= cutoff) {
                    int p = atomicAdd(&s_cand[r], 1);
                    if (p < CND) candCol[r][p] = idx * 8 + j;
                }
            }
        }
        sQ[r][tid4]       = g_Q[(size_t)row * DDIM + tid4];
        sQ[r][tid4 + 128] = g_Q[(size_t)row * DDIM + tid4 + 128];
        barx(r);
        if (s_cand[r] <= CND || ranFB) break;
        ranFB = true;
        unsigned pfx = 0;
        for (int bit = 31; bit >= 0; bit--) {
            unsigned t = pfx | (1u << bit);
            int c = 0;
            #pragma unroll
            for (int i = 0; i < 8; i++) {
                uint4 w = dst[tid4 + i * 128];
                float v[8];
                bf2f(w.x, v[0], v[1]); bf2f(w.y, v[2], v[3]);
                bf2f(w.z, v[4], v[5]); bf2f(w.w, v[6], v[7]);
                #pragma unroll
                for (int j = 0; j < 8; j++) c += (f2u(v[j]) >= t);
            }
            if (subSumI(c, red_i[r], r, w4, lane) >= KSEL) pfx = t;
        }
        if (tid4 == 0) { s_cutHi[r] = u2f(pfx); s_cand[r] = 0; }
        barx(r);
        cutHi = s_cutHi[r];
        cutoff = cutHi - 2.0f * EPS;
    }
    const int ncand = min(s_cand[r], CND);

    // ---- exact fp32 dots: 1 candidate per warp per iteration ----
    {
        const int e0 = lane * 8;
        const float* __restrict__ qrow = sQ[r] + e0;
        for (int cb = w4; cb < ncand; cb += 4) {          // warp-uniform trip
            const float* __restrict__ krow = g_K + (size_t)candCol[r][cb] * DDIM + e0;
            float4 q0 = *(const float4*)(qrow);
            float4 q1 = *(const float4*)(qrow + 4);
            float4 k0 = *(const float4*)(krow);
            float4 k1 = *(const float4*)(krow + 4);
            float part = q0.x * k0.x + q0.y * k0.y + q0.z * k0.z + q0.w * k0.w
                       + q1.x * k1.x + q1.y * k1.y + q1.z * k1.z + q1.w * k1.w;
            #pragma unroll
            for (int o = 16; o; o >>= 1) part += __shfl_down_sync(0xffffffffu, part, o);
            if (lane == 0) exS[r][cb] = part * scale;
        }
    }
    barx(r);

    // ---- exact ranking: thread handles candidates tid4 and tid4+128 ----
    int k0f = 0, k1f = 0;
    float ex0 = 0.f, ex1 = 0.f;
    {
        const int c0 = tid4, c1 = tid4 + 128;
        if (c0 < ncand) {
            float v = exS[r][c0];
            int cg = 0;
            for (int j = 0; j < ncand; j++) cg += (exS[r][j] > v);
            if (cg < KSEL) { k0f = 1; ex0 = expf(v - m); }
        }
        if (c1 < ncand) {
            float v = exS[r][c1];
            int cg = 0;
            for (int j = 0; j < ncand; j++) cg += (exS[r][j] > v);
            if (cg < KSEL) { k1f = 1; ex1 = expf(v - m); }
        }
    }

    // ---- deterministic two-segment ballot compaction ----
    int total;
    {
        unsigned b0 = __ballot_sync(0xffffffffu, k0f);
        unsigned b1 = __ballot_sync(0xffffffffu, k1f);
        if (lane == 0) { cw0[r][w4] = __popc(b0); cw1[r][w4] = __popc(b1); }
        barx(r);
        int base0 = 0, total0 = 0, base1pre = 0, total1 = 0;
        #pragma unroll
        for (int w = 0; w < 4; w++) {
            int c0c = cw0[r][w], c1c = cw1[r][w];
            if (w < w4) { base0 += c0c; base1pre += c1c; }
            total0 += c0c; total1 += c1c;
        }
        total = total0 + total1;
        unsigned ltm = (1u << lane) - 1u;
        if (k0f) {
            int slot = base0 + __popc(b0 & ltm);
            if (slot < SLOT_CAP) { sidx[r][slot] = candCol[r][tid4]; se[r][slot] = ex0; }
        }
        if (k1f) {
            int slot = total0 + base1pre + __popc(b1 & ltm);
            if (slot < SLOT_CAP) { sidx[r][slot] = candCol[r][tid4 + 128]; se[r][slot] = ex1; }
        }
    }

    float tot = subSumF((k0f ? ex0 : 0.f) + (k1f ? ex1 : 0.f), red_f[r], r, w4, lane);

    // ---- fused output gather: 4 row-groups x 2 dims per thread ----
    const int cnt = min(total, SLOT_CAP);
    const float inv = 1.0f / tot;
    const int d0 = tid4, d1 = tid4 + 128;

    float a0 = 0.f, a1 = 0.f, a2 = 0.f, a3 = 0.f;
    float b0a = 0.f, b1a = 0.f, b2a = 0.f, b3a = 0.f;
    int j = 0;
    for (; j + 4 <= cnt; j += 4) {
        const float* v0 = g_V + (size_t)sidx[r][j + 0] * DDIM;
        const float* v1 = g_V + (size_t)sidx[r][j + 1] * DDIM;
        const float* v2 = g_V + (size_t)sidx[r][j + 2] * DDIM;
        const float* v3 = g_V + (size_t)sidx[r][j + 3] * DDIM;
        a0  += se[r][j + 0] * v0[d0];  b0a += se[r][j + 0] * v0[d1];
        a1  += se[r][j + 1] * v1[d0];  b1a += se[r][j + 1] * v1[d1];
        a2  += se[r][j + 2] * v2[d0];  b2a += se[r][j + 2] * v2[d1];
        a3  += se[r][j + 3] * v3[d0];  b3a += se[r][j + 3] * v3[d1];
    }
    for (; j < cnt; j++) {
        const float* v0 = g_V + (size_t)sidx[r][j] * DDIM;
        a0  += se[r][j] * v0[d0];
        b0a += se[r][j] * v0[d1];
    }

    out[(size_t)row * DDIM + d0] = ((a0 + a1) + (a2 + a3)) * inv;
    out[(size_t)row * DDIM + d1] = ((b0a + b1a) + (b2a + b3a)) * inv;
}

// ---------------- launch ----------------
extern "C" void kernel_launch(void* const* d_in, const int* in_sizes, int n_in,
                              void* d_out, int out_size)
{
    const float* X    = (const float*)d_in[0];
    const float* Wq   = (const float*)d_in[1];
    const float* bq   = (const float*)d_in[2];
    const float* Wk   = (const float*)d_in[3];
    const float* bk   = (const float*)d_in[4];
    const float* Wv   = (const float*)d_in[5];
    const float* bv   = (const float*)d_in[6];
    const float* temp = (const float*)d_in[7];
    float* out = (float*)d_out;

    cudaFuncSetAttribute(score_mma_kernel,
                         cudaFuncAttributeMaxDynamicSharedMemorySize, SM_SCORE_TOTAL);

    dim3 blk(256);
    dim3 gQKV(DDIM / 128, NROWS / 128);
    qkv_kernel<<<gQKV, blk>>>(X, Wq, bq, 0);
    qkv_kernel<<<gQKV, blk>>>(X, Wk, bk, 1);
    qkv_kernel<<<gQKV, blk>>>(X, Wv, bv, 2);

    dim3 gS(NROWS / 128, NROWS / 128);
    score_mma_kernel<<<gS, blk, SM_SCORE_TOTAL>>>(temp);

    topk_out_kernel<<<NROWS / 2, blk>>>(temp, out);
}